// round 6
// baseline (speedup 1.0000x reference)
#include <cuda_runtime.h>
#include <cuda_fp16.h>
#include <math.h>
#include <stdint.h>

#define BB 8
#define SS 4096
#define EE 2048
#define DD 128
#define MM (BB*SS)   // 32768

#define LOG2E 1.44269504088896340736f

// fp16 hi/lo scratch (allocation-free __device__ globals)
__device__ __half g_xh[MM*EE];    // x split hi
__device__ __half g_xl[MM*EE];    // x split lo
__device__ __half g_qh[MM*DD];    // q scaled by log2e
__device__ __half g_ql[MM*DD];
__device__ __half g_kh[MM*DD];
__device__ __half g_kl[MM*DD];
__device__ __half g_vth[MM*DD];   // v transposed [b][d][s], hi only
// W transposed fp16 hi/lo: [y][d=128][e=2048]  (Wq pre-scaled by log2e)
__device__ __half g_wth[3*DD*EE];
__device__ __half g_wtl[3*DD*EE];

typedef unsigned long long u64;

__device__ __forceinline__ uint32_t pack_h2(float a, float b) {
    __half ha = __float2half_rn(a), hb = __float2half_rn(b);
    return ((uint32_t)__half_as_ushort(hb) << 16) | (uint32_t)__half_as_ushort(ha);
}
__device__ __forceinline__ uint32_t smem_u32(const void* p) {
    uint32_t a;
    asm("{ .reg .u64 t; cvta.to.shared.u64 t, %1; cvt.u32.u64 %0, t; }" : "=r"(a) : "l"(p));
    return a;
}
__device__ __forceinline__ float ex2(float x) {
    float r; asm("ex2.approx.f32 %0, %1;" : "=f"(r) : "f"(x)); return r;
}

// ---- sm_80-era primitives (valid on base compute_103) ----
__device__ __forceinline__ void cp16(uint32_t dst, const void* src) {
    asm volatile("cp.async.cg.shared.global [%0], [%1], 16;" :: "r"(dst), "l"(src));
}
#define CP_COMMIT() asm volatile("cp.async.commit_group;" ::: "memory")
#define CP_WAIT0()  asm volatile("cp.async.wait_group 0;" ::: "memory")

__device__ __forceinline__ void ldsm4(uint32_t r[4], uint32_t addr) {
    asm volatile("ldmatrix.sync.aligned.m8n8.x4.shared.b16 {%0,%1,%2,%3}, [%4];"
        : "=r"(r[0]), "=r"(r[1]), "=r"(r[2]), "=r"(r[3]) : "r"(addr));
}
__device__ __forceinline__ void mma16816(float c[4], const uint32_t a[4],
                                          uint32_t b0, uint32_t b1) {
    asm volatile("mma.sync.aligned.m16n8k16.row.col.f32.f16.f16.f32 "
        "{%0,%1,%2,%3}, {%4,%5,%6,%7}, {%8,%9}, {%0,%1,%2,%3};"
        : "+f"(c[0]), "+f"(c[1]), "+f"(c[2]), "+f"(c[3])
        : "r"(a[0]), "r"(a[1]), "r"(a[2]), "r"(a[3]), "r"(b0), "r"(b1));
}

// ============================================================================
// Kernel 0a: split x into fp16 hi/lo.
// ============================================================================
__global__ __launch_bounds__(256) void split_x(const float* __restrict__ x)
{
    long long idx = ((long long)blockIdx.x * 256 + threadIdx.x) * 4;
    float4 v = *(const float4*)(x + idx);
    float h0 = __half2float(__float2half_rn(v.x));
    float h1 = __half2float(__float2half_rn(v.y));
    float h2 = __half2float(__float2half_rn(v.z));
    float h3 = __half2float(__float2half_rn(v.w));
    *(uint2*)&g_xh[idx] = make_uint2(pack_h2(h0, h1), pack_h2(h2, h3));
    *(uint2*)&g_xl[idx] = make_uint2(pack_h2(v.x - h0, v.y - h1),
                                     pack_h2(v.z - h2, v.w - h3));
}

// ============================================================================
// Kernel 0b: split W (transposed, fp16 hi/lo).  Wq pre-scaled by log2e.
// ============================================================================
__global__ __launch_bounds__(256) void split_w(
    const float* __restrict__ Wq, const float* __restrict__ Wk,
    const float* __restrict__ Wv)
{
    int idx = blockIdx.x * 256 + threadIdx.x;
    int y = idx >> 18;
    int rem = idx & ((DD*EE) - 1);
    int d = rem >> 11;
    int e = rem & (EE - 1);
    const float* W = (y == 0) ? Wq : (y == 1) ? Wk : Wv;
    float v = W[(long long)e * DD + d];
    if (y == 0) v *= LOG2E;
    __half h = __float2half_rn(v);
    g_wth[idx] = h;
    g_wtl[idx] = __float2half_rn(v - __half2float(h));
}

// ============================================================================
// Kernel 1: QKV projection via mma.sync (q,k: 3 terms; v: 2 terms).
// ============================================================================
#define BK 64
#define XSTR 72
#define SXH 0
#define SXL (64*XSTR*2)
#define SWH (2*64*XSTR*2)
#define SWL (SWH + 128*XSTR*2)
#define QBUF (SWL + 128*XSTR*2)     // 55296
#define QKV_SMEM (2*QBUF)           // 110592
#define NCHUNK (EE/BK)              // 32

__device__ __forceinline__ void qkv_ld(uint32_t smem, int bufoff, int y,
                                       int m0, int kt, int tid) {
    long long xbase = (long long)m0 * EE + (long long)kt * BK;
    #pragma unroll
    for (int j = 0; j < 4; j++) {
        int idx = tid + j * 256;
        int hl = idx >> 9;
        int rem = idx & 511;
        int row = rem >> 3, c = rem & 7;
        const __half* src = (hl ? g_xl : g_xh) + xbase + (long long)row * EE + c * 8;
        cp16(smem + bufoff + (hl ? SXL : SXH) + row * (XSTR*2) + c * 16, src);
    }
    long long wbase = (long long)y * DD * EE + (long long)kt * BK;
    #pragma unroll
    for (int j = 0; j < 8; j++) {
        int idx = tid + j * 256;
        int hl = idx >> 10;
        int rem = idx & 1023;
        int n = rem >> 3, c = rem & 7;
        const __half* src = (hl ? g_wtl : g_wth) + wbase + (long long)n * EE + c * 8;
        cp16(smem + bufoff + (hl ? SWL : SWH) + n * (XSTR*2) + c * 16, src);
    }
}

__global__ __launch_bounds__(256, 2) void qkv_mma(
    const float* __restrict__ bq, const float* __restrict__ bk,
    const float* __restrict__ bv)
{
    extern __shared__ char sm[];
    const uint32_t smem = smem_u32(sm);
    const int tid = threadIdx.x;
    const int w = tid >> 5;
    const int l = tid & 31;
    const int y = blockIdx.y;
    const int m0 = blockIdx.x * 64;

    const int wm = (w >> 1) * 16;
    const int wn = (w & 1) * 64;
    const uint32_t brow  = (l & 7) + ((l >> 4) & 1) * 8;
    const uint32_t bcsel = ((l >> 3) & 1) * 16;

    float of[8][4];
    #pragma unroll
    for (int n = 0; n < 8; n++)
        #pragma unroll
        for (int c = 0; c < 4; c++) of[n][c] = 0.f;

    qkv_ld(smem, 0, y, m0, 0, tid);
    CP_COMMIT();
    CP_WAIT0();
    __syncthreads();

    int buf = 0;
    for (int kt = 0; kt < NCHUNK; kt++) {
        const int nb = buf ^ 1;
        if (kt + 1 < NCHUNK) {
            qkv_ld(smem, nb * QBUF, y, m0, kt + 1, tid);
            CP_COMMIT();
        }

        const uint32_t aoff = smem + buf * QBUF + SXH
                            + (wm + (l & 15)) * (XSTR*2) + (l >> 4) * 16;
        const uint32_t wb = smem + buf * QBUF + SWH;
        #pragma unroll
        for (int kc = 0; kc < 4; kc++) {
            uint32_t ah[4], al[4];
            ldsm4(ah, aoff + kc * 32);
            ldsm4(al, aoff + (SXL - SXH) + kc * 32);
            #pragma unroll
            for (int jp = 0; jp < 4; jp++) {
                uint32_t baddr = wb + (wn + jp*16 + brow) * (XSTR*2) + kc * 32 + bcsel;
                uint32_t bh[4];
                ldsm4(bh, baddr);
                mma16816(of[2*jp],   ah, bh[0], bh[1]);
                mma16816(of[2*jp+1], ah, bh[2], bh[3]);
                mma16816(of[2*jp],   al, bh[0], bh[1]);
                mma16816(of[2*jp+1], al, bh[2], bh[3]);
                if (y != 2) {
                    uint32_t bl2[4];
                    ldsm4(bl2, baddr + (SWL - SWH));
                    mma16816(of[2*jp],   ah, bl2[0], bl2[1]);
                    mma16816(of[2*jp+1], ah, bl2[2], bl2[3]);
                }
            }
        }

        if (kt + 1 < NCHUNK) CP_WAIT0();
        __syncthreads();
        buf = nb;
    }

    // epilogue: +bias (bq scaled by log2e), split hi/lo, store
    const float* bias = (y == 0) ? bq : (y == 1) ? bk : bv;
    const float bscale = (y == 0) ? LOG2E : 1.0f;
    const int row0 = m0 + wm + (l >> 2);
    const int row1 = row0 + 8;

    #pragma unroll
    for (int np = 0; np < 8; np++) {
        int col = wn + np * 8 + (l & 3) * 2;
        float b0 = bias[col] * bscale, b1 = bias[col + 1] * bscale;
        float v00 = of[np][0] + b0, v01 = of[np][1] + b1;
        float v10 = of[np][2] + b0, v11 = of[np][3] + b1;
        float h00 = __half2float(__float2half_rn(v00));
        float h01 = __half2float(__float2half_rn(v01));
        float h10 = __half2float(__float2half_rn(v10));
        float h11 = __half2float(__float2half_rn(v11));

        if (y < 2) {
            __half* ph = (y == 0) ? g_qh : g_kh;
            __half* pl = (y == 0) ? g_ql : g_kl;
            *(uint32_t*)&ph[(long long)row0 * DD + col] = pack_h2(h00, h01);
            *(uint32_t*)&ph[(long long)row1 * DD + col] = pack_h2(h10, h11);
            *(uint32_t*)&pl[(long long)row0 * DD + col] = pack_h2(v00 - h00, v01 - h01);
            *(uint32_t*)&pl[(long long)row1 * DD + col] = pack_h2(v10 - h10, v11 - h11);
        } else {
            int bbx0 = row0 >> 12, s0 = row0 & 4095;
            int bbx1 = row1 >> 12, s1 = row1 & 4095;
            g_vth[((long long)bbx0 * DD + col) * SS + s0]     = __float2half_rn(h00);
            g_vth[((long long)bbx0 * DD + col + 1) * SS + s0] = __float2half_rn(h01);
            g_vth[((long long)bbx1 * DD + col) * SS + s1]     = __float2half_rn(h10);
            g_vth[((long long)bbx1 * DD + col + 1) * SS + s1] = __float2half_rn(h11);
        }
    }
}

// ============================================================================
// Kernel 2: mma.sync flash attention, software-pipelined:
//   iter t: softmax(t) / PV(t)  -- S(t) was computed last iteration --
//           then wait load(t+1), sync, issue load(t+2), issue S(t+1).
// Scores arrive pre-scaled by log2e -> ex2 softmax.
// ============================================================================
#define QT 128
#define KT 64
#define NTILE (SS/KT)   // 64
#define QSTR 136
#define KSTR 136
#define VSTR 72

#define OFF_QH 0
#define OFF_QL (128*QSTR*2)
#define OFF_K  (OFF_QL + 128*QSTR*2)
#define KBUF   (64*KSTR*2*2)
#define KLOFF  (64*KSTR*2)
#define OFF_V  (OFF_K + 2*KBUF)
#define VBUF   (128*VSTR*2)
#define FLASH_SMEM (OFF_V + 2*VBUF)     // 176128

__device__ __forceinline__ void load_kv(uint32_t smem, int b, int kt, int buf, int tid) {
    long long tok0 = (long long)b * SS + (long long)kt * KT;
    #pragma unroll
    for (int it = 0; it < 8; it++) {
        int ci = tid + it * 256;
        int c = ci & 15;
        int row = (ci >> 4) & 63;
        const __half* src = ((ci < 1024) ? g_kh : g_kl) + (tok0 + row) * DD + c * 8;
        uint32_t dst = smem + OFF_K + buf * KBUF + ((ci < 1024) ? 0 : KLOFF)
                       + row * (KSTR*2) + c * 16;
        cp16(dst, src);
    }
    long long vbase = (long long)b * DD * SS + (long long)kt * KT;
    #pragma unroll
    for (int it = 0; it < 4; it++) {
        int ci = tid + it * 256;
        int c = ci & 7;
        int d = (ci >> 3) & 127;
        const __half* src = g_vth + vbase + (long long)d * SS + c * 8;
        uint32_t dst = smem + OFF_V + buf * VBUF + d * (VSTR*2) + c * 16;
        cp16(dst, src);
    }
}

// S = Qh*Kh + Ql*Kh + Qh*Kl into sf (overwrites).
__device__ __forceinline__ void compute_S(float sf[8][4], uint32_t qoff, uint32_t kb,
                                          uint32_t brow, uint32_t bcsel) {
    #pragma unroll
    for (int j = 0; j < 8; j++)
        #pragma unroll
        for (int c = 0; c < 4; c++) sf[j][c] = 0.f;
    #pragma unroll
    for (int kc = 0; kc < 8; kc++) {
        uint32_t ah[4], al[4];
        ldsm4(ah, qoff + OFF_QH + kc * 32);
        ldsm4(al, qoff + OFF_QL + kc * 32);
        #pragma unroll
        for (int jp = 0; jp < 4; jp++) {
            uint32_t baddr = kb + (jp*16 + brow) * (KSTR*2) + kc * 32 + bcsel;
            uint32_t bh[4], blr[4];
            ldsm4(bh, baddr);
            ldsm4(blr, baddr + KLOFF);
            mma16816(sf[2*jp],   ah, bh[0], bh[1]);
            mma16816(sf[2*jp+1], ah, bh[2], bh[3]);
            mma16816(sf[2*jp],   al, bh[0], bh[1]);
            mma16816(sf[2*jp+1], al, bh[2], bh[3]);
            mma16816(sf[2*jp],   ah, blr[0], blr[1]);
            mma16816(sf[2*jp+1], ah, blr[2], blr[3]);
        }
    }
}

__global__ __launch_bounds__(256, 1) void flash_attn(float* __restrict__ out)
{
    extern __shared__ char sm[];
    const uint32_t smem = smem_u32(sm);
    const int tid = threadIdx.x;
    const int w = tid >> 5;
    const int l = tid & 31;
    const int b = blockIdx.y;
    const int qi0 = blockIdx.x * QT;

    // prologue: Q + KV(0)
    {
        long long tok0 = (long long)b * SS + qi0;
        #pragma unroll
        for (int it = 0; it < 16; it++) {
            int ci = tid + it * 256;
            int c = ci & 15;
            int row = (ci >> 4) & 127;
            const __half* src = ((ci < 2048) ? g_qh : g_ql) + (tok0 + row) * DD + c * 8;
            uint32_t dst = smem + ((ci < 2048) ? OFF_QH : OFF_QL) + row * (QSTR*2) + c * 16;
            cp16(dst, src);
        }
    }
    load_kv(smem, b, 0, 0, tid);
    CP_COMMIT();
    CP_WAIT0();
    __syncthreads();

    float of[16][4];
    #pragma unroll
    for (int n = 0; n < 16; n++)
        #pragma unroll
        for (int c = 0; c < 4; c++) of[n][c] = 0.f;
    float m0 = -INFINITY, m1 = -INFINITY, l0 = 0.f, l1 = 0.f;

    const uint32_t qoff  = smem + (w*16 + (l & 15)) * (QSTR*2) + ((l >> 4) * 16);
    const uint32_t brow  = (l & 7) + ((l >> 4) & 1) * 8;
    const uint32_t bcsel = ((l >> 3) & 1) * 16;

    // kick off load(1), then compute S(0) (overlapped)
    load_kv(smem, b, 1, 1, tid);
    CP_COMMIT();
    float sf[8][4];
    compute_S(sf, qoff, smem + OFF_K, brow, bcsel);

    for (int t = 0; t < NTILE; t++) {
        const uint32_t vb = smem + OFF_V + (t & 1) * VBUF;

        // ---- softmax(t): max phase ----
        float mx0 = sf[0][0], mx1 = sf[0][2];
        #pragma unroll
        for (int j = 0; j < 8; j++) {
            mx0 = fmaxf(mx0, fmaxf(sf[j][0], sf[j][1]));
            mx1 = fmaxf(mx1, fmaxf(sf[j][2], sf[j][3]));
        }
        mx0 = fmaxf(mx0, __shfl_xor_sync(0xffffffffu, mx0, 1));
        mx0 = fmaxf(mx0, __shfl_xor_sync(0xffffffffu, mx0, 2));
        mx1 = fmaxf(mx1, __shfl_xor_sync(0xffffffffu, mx1, 1));
        mx1 = fmaxf(mx1, __shfl_xor_sync(0xffffffffu, mx1, 2));

        float mn0 = fmaxf(m0, mx0), mn1 = fmaxf(m1, mx1);
        float alpha0 = ex2(m0 - mn0), alpha1 = ex2(m1 - mn1);
        m0 = mn0; m1 = mn1;

        // ---- exp (scores already in log2 domain) ----
        float s0 = 0.f, s1 = 0.f;
        #pragma unroll
        for (int j = 0; j < 8; j++) {
            sf[j][0] = ex2(sf[j][0] - mn0); s0 += sf[j][0];
            sf[j][1] = ex2(sf[j][1] - mn0); s0 += sf[j][1];
            sf[j][2] = ex2(sf[j][2] - mn1); s1 += sf[j][2];
            sf[j][3] = ex2(sf[j][3] - mn1); s1 += sf[j][3];
        }

        // ---- rescale O ----
        #pragma unroll
        for (int n = 0; n < 16; n++) {
            of[n][0] *= alpha0; of[n][1] *= alpha0;
            of[n][2] *= alpha1; of[n][3] *= alpha1;
        }

        // ---- PV(t) ----
        #pragma unroll
        for (int jk = 0; jk < 4; jk++) {
            uint32_t ph[4], pl4[4];
            {
                float p00 = sf[2*jk][0],   p01 = sf[2*jk][1];
                float p02 = sf[2*jk][2],   p03 = sf[2*jk][3];
                float p10 = sf[2*jk+1][0], p11 = sf[2*jk+1][1];
                float p12 = sf[2*jk+1][2], p13 = sf[2*jk+1][3];
                float h00 = __half2float(__float2half_rn(p00));
                float h01 = __half2float(__float2half_rn(p01));
                float h02 = __half2float(__float2half_rn(p02));
                float h03 = __half2float(__float2half_rn(p03));
                float h10 = __half2float(__float2half_rn(p10));
                float h11 = __half2float(__float2half_rn(p11));
                float h12 = __half2float(__float2half_rn(p12));
                float h13 = __half2float(__float2half_rn(p13));
                ph[0] = pack_h2(h00, h01); ph[1] = pack_h2(h02, h03);
                ph[2] = pack_h2(h10, h11); ph[3] = pack_h2(h12, h13);
                pl4[0] = pack_h2(p00-h00, p01-h01); pl4[1] = pack_h2(p02-h02, p03-h03);
                pl4[2] = pack_h2(p10-h10, p11-h11); pl4[3] = pack_h2(p12-h12, p13-h13);
            }
            #pragma unroll
            for (int np = 0; np < 8; np++) {
                uint32_t vaddr = vb + (np*16 + brow) * (VSTR*2) + jk * 32 + bcsel;
                uint32_t vh[4];
                ldsm4(vh, vaddr);
                mma16816(of[2*np],   ph,  vh[0], vh[1]);
                mma16816(of[2*np+1], ph,  vh[2], vh[3]);
                mma16816(of[2*np],   pl4, vh[0], vh[1]);
                mma16816(of[2*np+1], pl4, vh[2], vh[3]);
            }
        }

        // ---- finish l reduction (overlaps PV drain) ----
        s0 += __shfl_xor_sync(0xffffffffu, s0, 1);
        s0 += __shfl_xor_sync(0xffffffffu, s0, 2);
        s1 += __shfl_xor_sync(0xffffffffu, s1, 1);
        s1 += __shfl_xor_sync(0xffffffffu, s1, 2);
        l0 = l0 * alpha0 + s0;
        l1 = l1 * alpha1 + s1;

        // ---- pipeline bookkeeping ----
        if (t + 1 < NTILE) CP_WAIT0();        // load(t+1) complete
        __syncthreads();                       // V(t) reads retired, load visible
        if (t + 2 < NTILE) {                   // prefetch t+2 into buf[t&1]
            load_kv(smem, b, t + 2, t & 1, tid);
            CP_COMMIT();
        }
        if (t + 1 < NTILE)                     // queue S(t+1) — overlaps next softmax
            compute_S(sf, qoff, smem + OFF_K + ((t + 1) & 1) * KBUF, brow, bcsel);
    }

    // ---- epilogue ----
    const int row0 = w*16 + (l >> 2);
    const float inv0 = 1.0f / l0, inv1 = 1.0f / l1;
    long long base0 = ((long long)b * SS + qi0 + row0) * DD;
    long long base1 = base0 + 8LL * DD;
    #pragma unroll
    for (int n = 0; n < 16; n++) {
        int cc = n*8 + (l & 3)*2;
        *(float2*)(out + base0 + cc) = make_float2(of[n][0]*inv0, of[n][1]*inv0);
        *(float2*)(out + base1 + cc) = make_float2(of[n][2]*inv1, of[n][3]*inv1);
    }
}

// ============================================================================
// launch
// ============================================================================
extern "C" void kernel_launch(void* const* d_in, const int* in_sizes, int n_in,
                              void* d_out, int out_size)
{
    const float* x  = (const float*)d_in[0];
    const float* Wq = (const float*)d_in[1];
    const float* bq = (const float*)d_in[2];
    const float* Wk = (const float*)d_in[3];
    const float* bk = (const float*)d_in[4];
    const float* Wv = (const float*)d_in[5];
    const float* bv = (const float*)d_in[6];
    float* out = (float*)d_out;

    split_x<<<(long long)MM*EE/1024, 256>>>(x);
    split_w<<<(3*DD*EE)/256, 256>>>(Wq, Wk, Wv);

    cudaFuncSetAttribute(qkv_mma, cudaFuncAttributeMaxDynamicSharedMemorySize,
                         QKV_SMEM);
    qkv_mma<<<dim3(MM/64, 3), 256, QKV_SMEM>>>(bq, bk, bv);

    cudaFuncSetAttribute(flash_attn, cudaFuncAttributeMaxDynamicSharedMemorySize,
                         FLASH_SMEM);
    flash_attn<<<dim3(SS / QT, BB), 256, FLASH_SMEM>>>(out);
}

// round 7
// speedup vs baseline: 1.0084x; 1.0084x over previous
#include <cuda_runtime.h>
#include <cuda_fp16.h>
#include <math.h>
#include <stdint.h>

#define BB 8
#define SS 4096
#define EE 2048
#define DD 128
#define MM (BB*SS)   // 32768

#define LOG2E 1.44269504088896340736f

// fp16 hi/lo scratch (allocation-free __device__ globals)
__device__ __half g_xh[MM*EE];
__device__ __half g_xl[MM*EE];
__device__ __half g_qh[MM*DD];    // q scaled by log2e
__device__ __half g_ql[MM*DD];
__device__ __half g_kh[MM*DD];
__device__ __half g_kl[MM*DD];
__device__ __half g_vth[MM*DD];   // v transposed [b][d][s], hi only
__device__ __half g_wth[3*DD*EE]; // W transposed hi (Wq pre-scaled by log2e)
__device__ __half g_wtl[3*DD*EE];

typedef unsigned long long u64;

__device__ __forceinline__ uint32_t pack_h2(float a, float b) {
    __half ha = __float2half_rn(a), hb = __float2half_rn(b);
    return ((uint32_t)__half_as_ushort(hb) << 16) | (uint32_t)__half_as_ushort(ha);
}
__device__ __forceinline__ uint32_t smem_u32(const void* p) {
    uint32_t a;
    asm("{ .reg .u64 t; cvta.to.shared.u64 t, %1; cvt.u32.u64 %0, t; }" : "=r"(a) : "l"(p));
    return a;
}
__device__ __forceinline__ float ex2(float x) {
    float r; asm("ex2.approx.f32 %0, %1;" : "=f"(r) : "f"(x)); return r;
}

__device__ __forceinline__ void cp16(uint32_t dst, const void* src) {
    asm volatile("cp.async.cg.shared.global [%0], [%1], 16;" :: "r"(dst), "l"(src));
}
#define CP_COMMIT() asm volatile("cp.async.commit_group;" ::: "memory")
#define CP_WAIT0()  asm volatile("cp.async.wait_group 0;" ::: "memory")

__device__ __forceinline__ void ldsm4(uint32_t r[4], uint32_t addr) {
    asm volatile("ldmatrix.sync.aligned.m8n8.x4.shared.b16 {%0,%1,%2,%3}, [%4];"
        : "=r"(r[0]), "=r"(r[1]), "=r"(r[2]), "=r"(r[3]) : "r"(addr));
}
__device__ __forceinline__ void mma16816(float c[4], const uint32_t a[4],
                                          uint32_t b0, uint32_t b1) {
    asm volatile("mma.sync.aligned.m16n8k16.row.col.f32.f16.f16.f32 "
        "{%0,%1,%2,%3}, {%4,%5,%6,%7}, {%8,%9}, {%0,%1,%2,%3};"
        : "+f"(c[0]), "+f"(c[1]), "+f"(c[2]), "+f"(c[3])
        : "r"(a[0]), "r"(a[1]), "r"(a[2]), "r"(a[3]), "r"(b0), "r"(b1));
}

// ============================================================================
// Kernel 0a: split x into fp16 hi/lo.
// ============================================================================
__global__ __launch_bounds__(256) void split_x(const float* __restrict__ x)
{
    long long idx = ((long long)blockIdx.x * 256 + threadIdx.x) * 4;
    float4 v = *(const float4*)(x + idx);
    float h0 = __half2float(__float2half_rn(v.x));
    float h1 = __half2float(__float2half_rn(v.y));
    float h2 = __half2float(__float2half_rn(v.z));
    float h3 = __half2float(__float2half_rn(v.w));
    *(uint2*)&g_xh[idx] = make_uint2(pack_h2(h0, h1), pack_h2(h2, h3));
    *(uint2*)&g_xl[idx] = make_uint2(pack_h2(v.x - h0, v.y - h1),
                                     pack_h2(v.z - h2, v.w - h3));
}

// ============================================================================
// Kernel 0b: split W (transposed, fp16 hi/lo).  Wq pre-scaled by log2e.
// ============================================================================
__global__ __launch_bounds__(256) void split_w(
    const float* __restrict__ Wq, const float* __restrict__ Wk,
    const float* __restrict__ Wv)
{
    int idx = blockIdx.x * 256 + threadIdx.x;
    int y = idx >> 18;
    int rem = idx & ((DD*EE) - 1);
    int d = rem >> 11;
    int e = rem & (EE - 1);
    const float* W = (y == 0) ? Wq : (y == 1) ? Wk : Wv;
    float v = W[(long long)e * DD + d];
    if (y == 0) v *= LOG2E;
    __half h = __float2half_rn(v);
    g_wth[idx] = h;
    g_wtl[idx] = __float2half_rn(v - __half2float(h));
}

// ============================================================================
// Kernel 1: QKV projection via mma.sync (unchanged from round 6).
// ============================================================================
#define BK 64
#define XSTR 72
#define SXH 0
#define SXL (64*XSTR*2)
#define SWH (2*64*XSTR*2)
#define SWL (SWH + 128*XSTR*2)
#define QBUF (SWL + 128*XSTR*2)     // 55296
#define QKV_SMEM (2*QBUF)           // 110592
#define NCHUNK (EE/BK)              // 32

__device__ __forceinline__ void qkv_ld(uint32_t smem, int bufoff, int y,
                                       int m0, int kt, int tid) {
    long long xbase = (long long)m0 * EE + (long long)kt * BK;
    #pragma unroll
    for (int j = 0; j < 4; j++) {
        int idx = tid + j * 256;
        int hl = idx >> 9;
        int rem = idx & 511;
        int row = rem >> 3, c = rem & 7;
        const __half* src = (hl ? g_xl : g_xh) + xbase + (long long)row * EE + c * 8;
        cp16(smem + bufoff + (hl ? SXL : SXH) + row * (XSTR*2) + c * 16, src);
    }
    long long wbase = (long long)y * DD * EE + (long long)kt * BK;
    #pragma unroll
    for (int j = 0; j < 8; j++) {
        int idx = tid + j * 256;
        int hl = idx >> 10;
        int rem = idx & 1023;
        int n = rem >> 3, c = rem & 7;
        const __half* src = (hl ? g_wtl : g_wth) + wbase + (long long)n * EE + c * 8;
        cp16(smem + bufoff + (hl ? SWL : SWH) + n * (XSTR*2) + c * 16, src);
    }
}

__global__ __launch_bounds__(256, 2) void qkv_mma(
    const float* __restrict__ bq, const float* __restrict__ bk,
    const float* __restrict__ bv)
{
    extern __shared__ char sm[];
    const uint32_t smem = smem_u32(sm);
    const int tid = threadIdx.x;
    const int w = tid >> 5;
    const int l = tid & 31;
    const int y = blockIdx.y;
    const int m0 = blockIdx.x * 64;

    const int wm = (w >> 1) * 16;
    const int wn = (w & 1) * 64;
    const uint32_t brow  = (l & 7) + ((l >> 4) & 1) * 8;
    const uint32_t bcsel = ((l >> 3) & 1) * 16;

    float of[8][4];
    #pragma unroll
    for (int n = 0; n < 8; n++)
        #pragma unroll
        for (int c = 0; c < 4; c++) of[n][c] = 0.f;

    qkv_ld(smem, 0, y, m0, 0, tid);
    CP_COMMIT();
    CP_WAIT0();
    __syncthreads();

    int buf = 0;
    for (int kt = 0; kt < NCHUNK; kt++) {
        const int nb = buf ^ 1;
        if (kt + 1 < NCHUNK) {
            qkv_ld(smem, nb * QBUF, y, m0, kt + 1, tid);
            CP_COMMIT();
        }

        const uint32_t aoff = smem + buf * QBUF + SXH
                            + (wm + (l & 15)) * (XSTR*2) + (l >> 4) * 16;
        const uint32_t wb = smem + buf * QBUF + SWH;
        #pragma unroll
        for (int kc = 0; kc < 4; kc++) {
            uint32_t ah[4], al[4];
            ldsm4(ah, aoff + kc * 32);
            ldsm4(al, aoff + (SXL - SXH) + kc * 32);
            #pragma unroll
            for (int jp = 0; jp < 4; jp++) {
                uint32_t baddr = wb + (wn + jp*16 + brow) * (XSTR*2) + kc * 32 + bcsel;
                uint32_t bh[4];
                ldsm4(bh, baddr);
                mma16816(of[2*jp],   ah, bh[0], bh[1]);
                mma16816(of[2*jp+1], ah, bh[2], bh[3]);
                mma16816(of[2*jp],   al, bh[0], bh[1]);
                mma16816(of[2*jp+1], al, bh[2], bh[3]);
                if (y != 2) {
                    uint32_t bl2[4];
                    ldsm4(bl2, baddr + (SWL - SWH));
                    mma16816(of[2*jp],   ah, bl2[0], bl2[1]);
                    mma16816(of[2*jp+1], ah, bl2[2], bl2[3]);
                }
            }
        }

        if (kt + 1 < NCHUNK) CP_WAIT0();
        __syncthreads();
        buf = nb;
    }

    const float* bias = (y == 0) ? bq : (y == 1) ? bk : bv;
    const float bscale = (y == 0) ? LOG2E : 1.0f;
    const int row0 = m0 + wm + (l >> 2);
    const int row1 = row0 + 8;

    #pragma unroll
    for (int np = 0; np < 8; np++) {
        int col = wn + np * 8 + (l & 3) * 2;
        float b0 = bias[col] * bscale, b1 = bias[col + 1] * bscale;
        float v00 = of[np][0] + b0, v01 = of[np][1] + b1;
        float v10 = of[np][2] + b0, v11 = of[np][3] + b1;
        float h00 = __half2float(__float2half_rn(v00));
        float h01 = __half2float(__float2half_rn(v01));
        float h10 = __half2float(__float2half_rn(v10));
        float h11 = __half2float(__float2half_rn(v11));

        if (y < 2) {
            __half* ph = (y == 0) ? g_qh : g_kh;
            __half* pl = (y == 0) ? g_ql : g_kl;
            *(uint32_t*)&ph[(long long)row0 * DD + col] = pack_h2(h00, h01);
            *(uint32_t*)&ph[(long long)row1 * DD + col] = pack_h2(h10, h11);
            *(uint32_t*)&pl[(long long)row0 * DD + col] = pack_h2(v00 - h00, v01 - h01);
            *(uint32_t*)&pl[(long long)row1 * DD + col] = pack_h2(v10 - h10, v11 - h11);
        } else {
            int bbx0 = row0 >> 12, s0 = row0 & 4095;
            int bbx1 = row1 >> 12, s1 = row1 & 4095;
            g_vth[((long long)bbx0 * DD + col) * SS + s0]     = __float2half_rn(h00);
            g_vth[((long long)bbx0 * DD + col + 1) * SS + s0] = __float2half_rn(h01);
            g_vth[((long long)bbx1 * DD + col) * SS + s1]     = __float2half_rn(h10);
            g_vth[((long long)bbx1 * DD + col + 1) * SS + s1] = __float2half_rn(h11);
        }
    }
}

// ============================================================================
// Kernel 2: flash attention with REGISTER-double-buffered scores.
// iter t: issue loads(K(t+2),V(t+1)) ; S(t+1)->sfB ; softmax(t)+PV(t) on sfA ;
//         wait+sync ; swap. Softmax ALU has no deps on the S stream -> ptxas
//         interleaves it into the 320-HMMA burst.
// ============================================================================
#define QT 128
#define KT 64
#define NTILE (SS/KT)   // 64
#define QSTR 136
#define KSTR 136
#define VSTR 72

#define OFF_QH 0
#define OFF_QL (128*QSTR*2)
#define OFF_K  (OFF_QL + 128*QSTR*2)
#define KBUF   (64*KSTR*2*2)
#define KLOFF  (64*KSTR*2)
#define OFF_V  (OFF_K + 2*KBUF)
#define VBUF   (128*VSTR*2)
#define FLASH_SMEM (OFF_V + 2*VBUF)     // 176128

__device__ __forceinline__ void load_k(uint32_t smem, int b, int kt, int buf, int tid) {
    long long tok0 = (long long)b * SS + (long long)kt * KT;
    #pragma unroll
    for (int it = 0; it < 8; it++) {
        int ci = tid + it * 256;
        int c = ci & 15;
        int row = (ci >> 4) & 63;
        const __half* src = ((ci < 1024) ? g_kh : g_kl) + (tok0 + row) * DD + c * 8;
        uint32_t dst = smem + OFF_K + buf * KBUF + ((ci < 1024) ? 0 : KLOFF)
                       + row * (KSTR*2) + c * 16;
        cp16(dst, src);
    }
}
__device__ __forceinline__ void load_v(uint32_t smem, int b, int kt, int buf, int tid) {
    long long vbase = (long long)b * DD * SS + (long long)kt * KT;
    #pragma unroll
    for (int it = 0; it < 4; it++) {
        int ci = tid + it * 256;
        int c = ci & 7;
        int d = (ci >> 3) & 127;
        const __half* src = g_vth + vbase + (long long)d * SS + c * 8;
        uint32_t dst = smem + OFF_V + buf * VBUF + d * (VSTR*2) + c * 16;
        cp16(dst, src);
    }
}

__device__ __forceinline__ void compute_S(float sf[8][4], uint32_t qoff, uint32_t kb,
                                          uint32_t brow, uint32_t bcsel) {
    #pragma unroll
    for (int j = 0; j < 8; j++)
        #pragma unroll
        for (int c = 0; c < 4; c++) sf[j][c] = 0.f;
    #pragma unroll
    for (int kc = 0; kc < 8; kc++) {
        uint32_t ah[4], al[4];
        ldsm4(ah, qoff + OFF_QH + kc * 32);
        ldsm4(al, qoff + OFF_QL + kc * 32);
        #pragma unroll
        for (int jp = 0; jp < 4; jp++) {
            uint32_t baddr = kb + (jp*16 + brow) * (KSTR*2) + kc * 32 + bcsel;
            uint32_t bh[4], blr[4];
            ldsm4(bh, baddr);
            ldsm4(blr, baddr + KLOFF);
            mma16816(sf[2*jp],   ah, bh[0], bh[1]);
            mma16816(sf[2*jp+1], ah, bh[2], bh[3]);
            mma16816(sf[2*jp],   al, bh[0], bh[1]);
            mma16816(sf[2*jp+1], al, bh[2], bh[3]);
            mma16816(sf[2*jp],   ah, blr[0], blr[1]);
            mma16816(sf[2*jp+1], ah, blr[2], blr[3]);
        }
    }
}

// One pipeline stage: sfA = current tile scores (softmax+PV), sfB = next (S).
__device__ __forceinline__ void flash_iter(
    int t, float sfA[8][4], float sfB[8][4], float of[16][4],
    float& m0, float& m1, float& l0, float& l1,
    uint32_t smem, int b, int tid, uint32_t qoff, uint32_t brow, uint32_t bcsel)
{
    // 1. issue next loads (land by end of this iteration)
    if (t + 2 < NTILE) load_k(smem, b, t + 2, t & 1, tid);
    if (t + 1 < NTILE) load_v(smem, b, t + 1, (t + 1) & 1, tid);
    CP_COMMIT();

    // 2. S(t+1) -> sfB (no register deps on sfA)
    if (t + 1 < NTILE)
        compute_S(sfB, qoff, smem + OFF_K + ((t + 1) & 1) * KBUF, brow, bcsel);

    // 3. softmax(t) on sfA (inputs ready since last iteration)
    float mx0 = sfA[0][0], mx1 = sfA[0][2];
    #pragma unroll
    for (int j = 0; j < 8; j++) {
        mx0 = fmaxf(mx0, fmaxf(sfA[j][0], sfA[j][1]));
        mx1 = fmaxf(mx1, fmaxf(sfA[j][2], sfA[j][3]));
    }
    mx0 = fmaxf(mx0, __shfl_xor_sync(0xffffffffu, mx0, 1));
    mx0 = fmaxf(mx0, __shfl_xor_sync(0xffffffffu, mx0, 2));
    mx1 = fmaxf(mx1, __shfl_xor_sync(0xffffffffu, mx1, 1));
    mx1 = fmaxf(mx1, __shfl_xor_sync(0xffffffffu, mx1, 2));

    float mn0 = fmaxf(m0, mx0), mn1 = fmaxf(m1, mx1);
    float alpha0 = ex2(m0 - mn0), alpha1 = ex2(m1 - mn1);
    m0 = mn0; m1 = mn1;

    float s0 = 0.f, s1 = 0.f;
    #pragma unroll
    for (int j = 0; j < 8; j++) {
        sfA[j][0] = ex2(sfA[j][0] - mn0); s0 += sfA[j][0];
        sfA[j][1] = ex2(sfA[j][1] - mn0); s0 += sfA[j][1];
        sfA[j][2] = ex2(sfA[j][2] - mn1); s1 += sfA[j][2];
        sfA[j][3] = ex2(sfA[j][3] - mn1); s1 += sfA[j][3];
    }

    #pragma unroll
    for (int n = 0; n < 16; n++) {
        of[n][0] *= alpha0; of[n][1] *= alpha0;
        of[n][2] *= alpha1; of[n][3] *= alpha1;
    }

    // 4. PV(t)
    const uint32_t vb = smem + OFF_V + (t & 1) * VBUF;
    #pragma unroll
    for (int jk = 0; jk < 4; jk++) {
        uint32_t ph[4], pl4[4];
        {
            float p00 = sfA[2*jk][0],   p01 = sfA[2*jk][1];
            float p02 = sfA[2*jk][2],   p03 = sfA[2*jk][3];
            float p10 = sfA[2*jk+1][0], p11 = sfA[2*jk+1][1];
            float p12 = sfA[2*jk+1][2], p13 = sfA[2*jk+1][3];
            float h00 = __half2float(__float2half_rn(p00));
            float h01 = __half2float(__float2half_rn(p01));
            float h02 = __half2float(__float2half_rn(p02));
            float h03 = __half2float(__float2half_rn(p03));
            float h10 = __half2float(__float2half_rn(p10));
            float h11 = __half2float(__float2half_rn(p11));
            float h12 = __half2float(__float2half_rn(p12));
            float h13 = __half2float(__float2half_rn(p13));
            ph[0] = pack_h2(h00, h01); ph[1] = pack_h2(h02, h03);
            ph[2] = pack_h2(h10, h11); ph[3] = pack_h2(h12, h13);
            pl4[0] = pack_h2(p00-h00, p01-h01); pl4[1] = pack_h2(p02-h02, p03-h03);
            pl4[2] = pack_h2(p10-h10, p11-h11); pl4[3] = pack_h2(p12-h12, p13-h13);
        }
        #pragma unroll
        for (int np = 0; np < 8; np++) {
            uint32_t vaddr = vb + (np*16 + brow) * (VSTR*2) + jk * 32 + bcsel;
            uint32_t vh[4];
            ldsm4(vh, vaddr);
            mma16816(of[2*np],   ph,  vh[0], vh[1]);
            mma16816(of[2*np+1], ph,  vh[2], vh[3]);
            mma16816(of[2*np],   pl4, vh[0], vh[1]);
            mma16816(of[2*np+1], pl4, vh[2], vh[3]);
        }
    }

    // 5. l reduction tail
    s0 += __shfl_xor_sync(0xffffffffu, s0, 1);
    s0 += __shfl_xor_sync(0xffffffffu, s0, 2);
    s1 += __shfl_xor_sync(0xffffffffu, s1, 1);
    s1 += __shfl_xor_sync(0xffffffffu, s1, 2);
    l0 = l0 * alpha0 + s0;
    l1 = l1 * alpha1 + s1;

    // 6. retire loads issued at step 1; release buffers
    CP_WAIT0();
    __syncthreads();
}

__global__ __launch_bounds__(256, 1) void flash_attn(float* __restrict__ out)
{
    extern __shared__ char sm[];
    const uint32_t smem = smem_u32(sm);
    const int tid = threadIdx.x;
    const int w = tid >> 5;
    const int l = tid & 31;
    const int b = blockIdx.y;
    const int qi0 = blockIdx.x * QT;

    // prologue: Q + K(0) + V(0) + K(1)
    {
        long long tok0 = (long long)b * SS + qi0;
        #pragma unroll
        for (int it = 0; it < 16; it++) {
            int ci = tid + it * 256;
            int c = ci & 15;
            int row = (ci >> 4) & 127;
            const __half* src = ((ci < 2048) ? g_qh : g_ql) + (tok0 + row) * DD + c * 8;
            uint32_t dst = smem + ((ci < 2048) ? OFF_QH : OFF_QL) + row * (QSTR*2) + c * 16;
            cp16(dst, src);
        }
    }
    load_k(smem, b, 0, 0, tid);
    load_v(smem, b, 0, 0, tid);
    load_k(smem, b, 1, 1, tid);
    CP_COMMIT();
    CP_WAIT0();
    __syncthreads();

    float of[16][4];
    #pragma unroll
    for (int n = 0; n < 16; n++)
        #pragma unroll
        for (int c = 0; c < 4; c++) of[n][c] = 0.f;
    float m0 = -INFINITY, m1 = -INFINITY, l0 = 0.f, l1 = 0.f;

    const uint32_t qoff  = smem + (w*16 + (l & 15)) * (QSTR*2) + ((l >> 4) * 16);
    const uint32_t brow  = (l & 7) + ((l >> 4) & 1) * 8;
    const uint32_t bcsel = ((l >> 3) & 1) * 16;

    float sfA[8][4], sfB[8][4];
    compute_S(sfA, qoff, smem + OFF_K, brow, bcsel);   // S(0) from K(0)
    __syncthreads();                                    // K(0) dead for all warps

    #pragma unroll 1
    for (int t = 0; t < NTILE; t += 2) {
        flash_iter(t,     sfA, sfB, of, m0, m1, l0, l1, smem, b, tid, qoff, brow, bcsel);
        flash_iter(t + 1, sfB, sfA, of, m0, m1, l0, l1, smem, b, tid, qoff, brow, bcsel);
    }

    // epilogue
    const int row0 = w*16 + (l >> 2);
    const float inv0 = 1.0f / l0, inv1 = 1.0f / l1;
    long long base0 = ((long long)b * SS + qi0 + row0) * DD;
    long long base1 = base0 + 8LL * DD;
    #pragma unroll
    for (int n = 0; n < 16; n++) {
        int cc = n*8 + (l & 3)*2;
        *(float2*)(out + base0 + cc) = make_float2(of[n][0]*inv0, of[n][1]*inv0);
        *(float2*)(out + base1 + cc) = make_float2(of[n][2]*inv1, of[n][3]*inv1);
    }
}

// ============================================================================
// launch
// ============================================================================
extern "C" void kernel_launch(void* const* d_in, const int* in_sizes, int n_in,
                              void* d_out, int out_size)
{
    const float* x  = (const float*)d_in[0];
    const float* Wq = (const float*)d_in[1];
    const float* bq = (const float*)d_in[2];
    const float* Wk = (const float*)d_in[3];
    const float* bk = (const float*)d_in[4];
    const float* Wv = (const float*)d_in[5];
    const float* bv = (const float*)d_in[6];
    float* out = (float*)d_out;

    split_x<<<(long long)MM*EE/1024, 256>>>(x);
    split_w<<<(3*DD*EE)/256, 256>>>(Wq, Wk, Wv);

    cudaFuncSetAttribute(qkv_mma, cudaFuncAttributeMaxDynamicSharedMemorySize,
                         QKV_SMEM);
    qkv_mma<<<dim3(MM/64, 3), 256, QKV_SMEM>>>(bq, bk, bv);

    cudaFuncSetAttribute(flash_attn, cudaFuncAttributeMaxDynamicSharedMemorySize,
                         FLASH_SMEM);
    flash_attn<<<dim3(SS / QT, BB), 256, FLASH_SMEM>>>(out);
}

// round 8
// speedup vs baseline: 1.1024x; 1.0933x over previous
#include <cuda_runtime.h>
#include <cuda_fp16.h>
#include <math.h>
#include <stdint.h>

#define BB 8
#define SS 4096
#define EE 2048
#define DD 128
#define MM (BB*SS)   // 32768

#define LOG2E 1.44269504088896340736f

// fp16 hi/lo scratch (allocation-free __device__ globals)
__device__ __half g_xh[MM*EE];
__device__ __half g_xl[MM*EE];
__device__ __half g_qh[MM*DD];    // q scaled by log2e
__device__ __half g_ql[MM*DD];
__device__ __half g_kh[MM*DD];
__device__ __half g_kl[MM*DD];
__device__ __half g_vth[MM*DD];   // v transposed [b][d][s], hi only
__device__ __half g_wth[3*DD*EE]; // W transposed hi (Wq pre-scaled by log2e)
__device__ __half g_wtl[3*DD*EE];

typedef unsigned long long u64;

__device__ __forceinline__ uint32_t pack_h2(float a, float b) {
    __half ha = __float2half_rn(a), hb = __float2half_rn(b);
    return ((uint32_t)__half_as_ushort(hb) << 16) | (uint32_t)__half_as_ushort(ha);
}
// packed cvt: low half = a, high half = b (single SASS op)
__device__ __forceinline__ uint32_t cvt_h2(float a, float b) {
    uint32_t r;
    asm("cvt.rn.f16x2.f32 %0, %1, %2;" : "=r"(r) : "f"(b), "f"(a));
    return r;
}
__device__ __forceinline__ uint32_t smem_u32(const void* p) {
    uint32_t a;
    asm("{ .reg .u64 t; cvta.to.shared.u64 t, %1; cvt.u32.u64 %0, t; }" : "=r"(a) : "l"(p));
    return a;
}
__device__ __forceinline__ float ex2(float x) {
    float r; asm("ex2.approx.f32 %0, %1;" : "=f"(r) : "f"(x)); return r;
}

__device__ __forceinline__ void cp16(uint32_t dst, const void* src) {
    asm volatile("cp.async.cg.shared.global [%0], [%1], 16;" :: "r"(dst), "l"(src));
}
#define CP_COMMIT() asm volatile("cp.async.commit_group;" ::: "memory")
#define CP_WAIT0()  asm volatile("cp.async.wait_group 0;" ::: "memory")

__device__ __forceinline__ void ldsm4(uint32_t r[4], uint32_t addr) {
    asm volatile("ldmatrix.sync.aligned.m8n8.x4.shared.b16 {%0,%1,%2,%3}, [%4];"
        : "=r"(r[0]), "=r"(r[1]), "=r"(r[2]), "=r"(r[3]) : "r"(addr));
}
__device__ __forceinline__ void mma16816(float c[4], const uint32_t a[4],
                                          uint32_t b0, uint32_t b1) {
    asm volatile("mma.sync.aligned.m16n8k16.row.col.f32.f16.f16.f32 "
        "{%0,%1,%2,%3}, {%4,%5,%6,%7}, {%8,%9}, {%0,%1,%2,%3};"
        : "+f"(c[0]), "+f"(c[1]), "+f"(c[2]), "+f"(c[3])
        : "r"(a[0]), "r"(a[1]), "r"(a[2]), "r"(a[3]), "r"(b0), "r"(b1));
}

// ============================================================================
// Kernel 0a: split x into fp16 hi/lo.
// ============================================================================
__global__ __launch_bounds__(256) void split_x(const float* __restrict__ x)
{
    long long idx = ((long long)blockIdx.x * 256 + threadIdx.x) * 4;
    float4 v = *(const float4*)(x + idx);
    float h0 = __half2float(__float2half_rn(v.x));
    float h1 = __half2float(__float2half_rn(v.y));
    float h2 = __half2float(__float2half_rn(v.z));
    float h3 = __half2float(__float2half_rn(v.w));
    *(uint2*)&g_xh[idx] = make_uint2(pack_h2(h0, h1), pack_h2(h2, h3));
    *(uint2*)&g_xl[idx] = make_uint2(pack_h2(v.x - h0, v.y - h1),
                                     pack_h2(v.z - h2, v.w - h3));
}

// ============================================================================
// Kernel 0b: split W (transposed, fp16 hi/lo).  Wq pre-scaled by log2e.
// ============================================================================
__global__ __launch_bounds__(256) void split_w(
    const float* __restrict__ Wq, const float* __restrict__ Wk,
    const float* __restrict__ Wv)
{
    int idx = blockIdx.x * 256 + threadIdx.x;
    int y = idx >> 18;
    int rem = idx & ((DD*EE) - 1);
    int d = rem >> 11;
    int e = rem & (EE - 1);
    const float* W = (y == 0) ? Wq : (y == 1) ? Wk : Wv;
    float v = W[(long long)e * DD + d];
    if (y == 0) v *= LOG2E;
    __half h = __float2half_rn(v);
    g_wth[idx] = h;
    g_wtl[idx] = __float2half_rn(v - __half2float(h));
}

// ============================================================================
// Kernel 1: QKV projection via mma.sync (unchanged).
// ============================================================================
#define BK 64
#define XSTR 72
#define SXH 0
#define SXL (64*XSTR*2)
#define SWH (2*64*XSTR*2)
#define SWL (SWH + 128*XSTR*2)
#define QBUF (SWL + 128*XSTR*2)     // 55296
#define QKV_SMEM (2*QBUF)           // 110592
#define NCHUNK (EE/BK)              // 32

__device__ __forceinline__ void qkv_ld(uint32_t smem, int bufoff, int y,
                                       int m0, int kt, int tid) {
    long long xbase = (long long)m0 * EE + (long long)kt * BK;
    #pragma unroll
    for (int j = 0; j < 4; j++) {
        int idx = tid + j * 256;
        int hl = idx >> 9;
        int rem = idx & 511;
        int row = rem >> 3, c = rem & 7;
        const __half* src = (hl ? g_xl : g_xh) + xbase + (long long)row * EE + c * 8;
        cp16(smem + bufoff + (hl ? SXL : SXH) + row * (XSTR*2) + c * 16, src);
    }
    long long wbase = (long long)y * DD * EE + (long long)kt * BK;
    #pragma unroll
    for (int j = 0; j < 8; j++) {
        int idx = tid + j * 256;
        int hl = idx >> 10;
        int rem = idx & 1023;
        int n = rem >> 3, c = rem & 7;
        const __half* src = (hl ? g_wtl : g_wth) + wbase + (long long)n * EE + c * 8;
        cp16(smem + bufoff + (hl ? SWL : SWH) + n * (XSTR*2) + c * 16, src);
    }
}

__global__ __launch_bounds__(256, 2) void qkv_mma(
    const float* __restrict__ bq, const float* __restrict__ bk,
    const float* __restrict__ bv)
{
    extern __shared__ char sm[];
    const uint32_t smem = smem_u32(sm);
    const int tid = threadIdx.x;
    const int w = tid >> 5;
    const int l = tid & 31;
    const int y = blockIdx.y;
    const int m0 = blockIdx.x * 64;

    const int wm = (w >> 1) * 16;
    const int wn = (w & 1) * 64;
    const uint32_t brow  = (l & 7) + ((l >> 4) & 1) * 8;
    const uint32_t bcsel = ((l >> 3) & 1) * 16;

    float of[8][4];
    #pragma unroll
    for (int n = 0; n < 8; n++)
        #pragma unroll
        for (int c = 0; c < 4; c++) of[n][c] = 0.f;

    qkv_ld(smem, 0, y, m0, 0, tid);
    CP_COMMIT();
    CP_WAIT0();
    __syncthreads();

    int buf = 0;
    for (int kt = 0; kt < NCHUNK; kt++) {
        const int nb = buf ^ 1;
        if (kt + 1 < NCHUNK) {
            qkv_ld(smem, nb * QBUF, y, m0, kt + 1, tid);
            CP_COMMIT();
        }

        const uint32_t aoff = smem + buf * QBUF + SXH
                            + (wm + (l & 15)) * (XSTR*2) + (l >> 4) * 16;
        const uint32_t wb = smem + buf * QBUF + SWH;
        #pragma unroll
        for (int kc = 0; kc < 4; kc++) {
            uint32_t ah[4], al[4];
            ldsm4(ah, aoff + kc * 32);
            ldsm4(al, aoff + (SXL - SXH) + kc * 32);
            #pragma unroll
            for (int jp = 0; jp < 4; jp++) {
                uint32_t baddr = wb + (wn + jp*16 + brow) * (XSTR*2) + kc * 32 + bcsel;
                uint32_t bh[4];
                ldsm4(bh, baddr);
                mma16816(of[2*jp],   ah, bh[0], bh[1]);
                mma16816(of[2*jp+1], ah, bh[2], bh[3]);
                mma16816(of[2*jp],   al, bh[0], bh[1]);
                mma16816(of[2*jp+1], al, bh[2], bh[3]);
                if (y != 2) {
                    uint32_t bl2[4];
                    ldsm4(bl2, baddr + (SWL - SWH));
                    mma16816(of[2*jp],   ah, bl2[0], bl2[1]);
                    mma16816(of[2*jp+1], ah, bl2[2], bl2[3]);
                }
            }
        }

        if (kt + 1 < NCHUNK) CP_WAIT0();
        __syncthreads();
        buf = nb;
    }

    const float* bias = (y == 0) ? bq : (y == 1) ? bk : bv;
    const float bscale = (y == 0) ? LOG2E : 1.0f;
    const int row0 = m0 + wm + (l >> 2);
    const int row1 = row0 + 8;

    #pragma unroll
    for (int np = 0; np < 8; np++) {
        int col = wn + np * 8 + (l & 3) * 2;
        float b0 = bias[col] * bscale, b1 = bias[col + 1] * bscale;
        float v00 = of[np][0] + b0, v01 = of[np][1] + b1;
        float v10 = of[np][2] + b0, v11 = of[np][3] + b1;
        float h00 = __half2float(__float2half_rn(v00));
        float h01 = __half2float(__float2half_rn(v01));
        float h10 = __half2float(__float2half_rn(v10));
        float h11 = __half2float(__float2half_rn(v11));

        if (y < 2) {
            __half* ph = (y == 0) ? g_qh : g_kh;
            __half* pl = (y == 0) ? g_ql : g_kl;
            *(uint32_t*)&ph[(long long)row0 * DD + col] = pack_h2(h00, h01);
            *(uint32_t*)&ph[(long long)row1 * DD + col] = pack_h2(h10, h11);
            *(uint32_t*)&pl[(long long)row0 * DD + col] = pack_h2(v00 - h00, v01 - h01);
            *(uint32_t*)&pl[(long long)row1 * DD + col] = pack_h2(v10 - h10, v11 - h11);
        } else {
            int bbx0 = row0 >> 12, s0 = row0 & 4095;
            int bbx1 = row1 >> 12, s1 = row1 & 4095;
            g_vth[((long long)bbx0 * DD + col) * SS + s0]     = __float2half_rn(h00);
            g_vth[((long long)bbx0 * DD + col + 1) * SS + s0] = __float2half_rn(h01);
            g_vth[((long long)bbx1 * DD + col) * SS + s1]     = __float2half_rn(h10);
            g_vth[((long long)bbx1 * DD + col + 1) * SS + s1] = __float2half_rn(h11);
        }
    }
}

// ============================================================================
// Kernel 2: flash attention.
//   S  = Qh*Kh + Ql*Kh + Qh*Kl   (3 terms)
//   PV = P(fp16)*V(fp16)         (1 term: P rounded to fp16, err <= 2^-11)
// Lazy max (rescale only when max increases), per-thread partial l reduced
// once at epilogue. Register double-buffered scores (sfA/sfB).
// ============================================================================
#define QT 128
#define KT 64
#define NTILE (SS/KT)   // 64
#define QSTR 136
#define KSTR 136
#define VSTR 72

#define OFF_QH 0
#define OFF_QL (128*QSTR*2)
#define OFF_K  (OFF_QL + 128*QSTR*2)
#define KBUF   (64*KSTR*2*2)
#define KLOFF  (64*KSTR*2)
#define OFF_V  (OFF_K + 2*KBUF)
#define VBUF   (128*VSTR*2)
#define FLASH_SMEM (OFF_V + 2*VBUF)     // 176128

__device__ __forceinline__ void load_k(uint32_t smem, int b, int kt, int buf, int tid) {
    long long tok0 = (long long)b * SS + (long long)kt * KT;
    #pragma unroll
    for (int it = 0; it < 8; it++) {
        int ci = tid + it * 256;
        int c = ci & 15;
        int row = (ci >> 4) & 63;
        const __half* src = ((ci < 1024) ? g_kh : g_kl) + (tok0 + row) * DD + c * 8;
        uint32_t dst = smem + OFF_K + buf * KBUF + ((ci < 1024) ? 0 : KLOFF)
                       + row * (KSTR*2) + c * 16;
        cp16(dst, src);
    }
}
__device__ __forceinline__ void load_v(uint32_t smem, int b, int kt, int buf, int tid) {
    long long vbase = (long long)b * DD * SS + (long long)kt * KT;
    #pragma unroll
    for (int it = 0; it < 4; it++) {
        int ci = tid + it * 256;
        int c = ci & 7;
        int d = (ci >> 3) & 127;
        const __half* src = g_vth + vbase + (long long)d * SS + c * 8;
        uint32_t dst = smem + OFF_V + buf * VBUF + d * (VSTR*2) + c * 16;
        cp16(dst, src);
    }
}

__device__ __forceinline__ void compute_S(float sf[8][4], uint32_t qoff, uint32_t kb,
                                          uint32_t brow, uint32_t bcsel) {
    #pragma unroll
    for (int j = 0; j < 8; j++)
        #pragma unroll
        for (int c = 0; c < 4; c++) sf[j][c] = 0.f;
    #pragma unroll
    for (int kc = 0; kc < 8; kc++) {
        uint32_t ah[4], al[4];
        ldsm4(ah, qoff + OFF_QH + kc * 32);
        ldsm4(al, qoff + OFF_QL + kc * 32);
        #pragma unroll
        for (int jp = 0; jp < 4; jp++) {
            uint32_t baddr = kb + (jp*16 + brow) * (KSTR*2) + kc * 32 + bcsel;
            uint32_t bh[4], blr[4];
            ldsm4(bh, baddr);
            ldsm4(blr, baddr + KLOFF);
            mma16816(sf[2*jp],   ah, bh[0], bh[1]);
            mma16816(sf[2*jp+1], ah, bh[2], bh[3]);
            mma16816(sf[2*jp],   al, bh[0], bh[1]);
            mma16816(sf[2*jp+1], al, bh[2], bh[3]);
            mma16816(sf[2*jp],   ah, blr[0], blr[1]);
            mma16816(sf[2*jp+1], ah, blr[2], blr[3]);
        }
    }
}

__device__ __forceinline__ void flash_iter(
    int t, float sfA[8][4], float sfB[8][4], float of[16][4],
    float& m0, float& m1, float& l0, float& l1,
    uint32_t smem, int b, int tid, uint32_t qoff, uint32_t brow, uint32_t bcsel)
{
    // 1. issue next loads
    if (t + 2 < NTILE) load_k(smem, b, t + 2, t & 1, tid);
    if (t + 1 < NTILE) load_v(smem, b, t + 1, (t + 1) & 1, tid);
    CP_COMMIT();

    // 2. S(t+1) -> sfB (independent of sfA)
    if (t + 1 < NTILE)
        compute_S(sfB, qoff, smem + OFF_K + ((t + 1) & 1) * KBUF, brow, bcsel);

    // 3. lazy-max softmax(t) on sfA
    float mx0 = sfA[0][0], mx1 = sfA[0][2];
    #pragma unroll
    for (int j = 0; j < 8; j++) {
        mx0 = fmaxf(mx0, fmaxf(sfA[j][0], sfA[j][1]));
        mx1 = fmaxf(mx1, fmaxf(sfA[j][2], sfA[j][3]));
    }
    mx0 = fmaxf(mx0, __shfl_xor_sync(0xffffffffu, mx0, 1));
    mx0 = fmaxf(mx0, __shfl_xor_sync(0xffffffffu, mx0, 2));
    mx1 = fmaxf(mx1, __shfl_xor_sync(0xffffffffu, mx1, 1));
    mx1 = fmaxf(mx1, __shfl_xor_sync(0xffffffffu, mx1, 2));

    if (mx0 > m0) {                       // rare after the first few tiles
        float a = ex2(m0 - mx0);
        m0 = mx0;
        l0 *= a;
        #pragma unroll
        for (int n = 0; n < 16; n++) { of[n][0] *= a; of[n][1] *= a; }
    }
    if (mx1 > m1) {
        float a = ex2(m1 - mx1);
        m1 = mx1;
        l1 *= a;
        #pragma unroll
        for (int n = 0; n < 16; n++) { of[n][2] *= a; of[n][3] *= a; }
    }

    // exp + per-thread partial sums (no shfl here)
    #pragma unroll
    for (int j = 0; j < 8; j++) {
        sfA[j][0] = ex2(sfA[j][0] - m0); l0 += sfA[j][0];
        sfA[j][1] = ex2(sfA[j][1] - m0); l0 += sfA[j][1];
        sfA[j][2] = ex2(sfA[j][2] - m1); l1 += sfA[j][2];
        sfA[j][3] = ex2(sfA[j][3] - m1); l1 += sfA[j][3];
    }

    // 4. PV(t), single fp16 term
    const uint32_t vb = smem + OFF_V + (t & 1) * VBUF;
    #pragma unroll
    for (int jk = 0; jk < 4; jk++) {
        uint32_t ph[4];
        ph[0] = cvt_h2(sfA[2*jk][0],   sfA[2*jk][1]);
        ph[1] = cvt_h2(sfA[2*jk][2],   sfA[2*jk][3]);
        ph[2] = cvt_h2(sfA[2*jk+1][0], sfA[2*jk+1][1]);
        ph[3] = cvt_h2(sfA[2*jk+1][2], sfA[2*jk+1][3]);
        #pragma unroll
        for (int np = 0; np < 8; np++) {
            uint32_t vaddr = vb + (np*16 + brow) * (VSTR*2) + jk * 32 + bcsel;
            uint32_t vh[4];
            ldsm4(vh, vaddr);
            mma16816(of[2*np],   ph, vh[0], vh[1]);
            mma16816(of[2*np+1], ph, vh[2], vh[3]);
        }
    }

    // 5. retire loads, release buffers
    CP_WAIT0();
    __syncthreads();
}

__global__ __launch_bounds__(256, 1) void flash_attn(float* __restrict__ out)
{
    extern __shared__ char sm[];
    const uint32_t smem = smem_u32(sm);
    const int tid = threadIdx.x;
    const int w = tid >> 5;
    const int l = tid & 31;
    const int b = blockIdx.y;
    const int qi0 = blockIdx.x * QT;

    // prologue: Q + K(0) + V(0) + K(1)
    {
        long long tok0 = (long long)b * SS + qi0;
        #pragma unroll
        for (int it = 0; it < 16; it++) {
            int ci = tid + it * 256;
            int c = ci & 15;
            int row = (ci >> 4) & 127;
            const __half* src = ((ci < 2048) ? g_qh : g_ql) + (tok0 + row) * DD + c * 8;
            uint32_t dst = smem + ((ci < 2048) ? OFF_QH : OFF_QL) + row * (QSTR*2) + c * 16;
            cp16(dst, src);
        }
    }
    load_k(smem, b, 0, 0, tid);
    load_v(smem, b, 0, 0, tid);
    load_k(smem, b, 1, 1, tid);
    CP_COMMIT();
    CP_WAIT0();
    __syncthreads();

    float of[16][4];
    #pragma unroll
    for (int n = 0; n < 16; n++)
        #pragma unroll
        for (int c = 0; c < 4; c++) of[n][c] = 0.f;
    float m0 = -INFINITY, m1 = -INFINITY, l0 = 0.f, l1 = 0.f;

    const uint32_t qoff  = smem + (w*16 + (l & 15)) * (QSTR*2) + ((l >> 4) * 16);
    const uint32_t brow  = (l & 7) + ((l >> 4) & 1) * 8;
    const uint32_t bcsel = ((l >> 3) & 1) * 16;

    float sfA[8][4], sfB[8][4];
    compute_S(sfA, qoff, smem + OFF_K, brow, bcsel);   // S(0) from K(0)
    __syncthreads();                                    // K(0) dead for all warps

    #pragma unroll 1
    for (int t = 0; t < NTILE; t += 2) {
        flash_iter(t,     sfA, sfB, of, m0, m1, l0, l1, smem, b, tid, qoff, brow, bcsel);
        flash_iter(t + 1, sfB, sfA, of, m0, m1, l0, l1, smem, b, tid, qoff, brow, bcsel);
    }

    // epilogue: finish the deferred l reduction, normalize, store
    l0 += __shfl_xor_sync(0xffffffffu, l0, 1);
    l0 += __shfl_xor_sync(0xffffffffu, l0, 2);
    l1 += __shfl_xor_sync(0xffffffffu, l1, 1);
    l1 += __shfl_xor_sync(0xffffffffu, l1, 2);

    const int row0 = w*16 + (l >> 2);
    const float inv0 = 1.0f / l0, inv1 = 1.0f / l1;
    long long base0 = ((long long)b * SS + qi0 + row0) * DD;
    long long base1 = base0 + 8LL * DD;
    #pragma unroll
    for (int n = 0; n < 16; n++) {
        int cc = n*8 + (l & 3)*2;
        *(float2*)(out + base0 + cc) = make_float2(of[n][0]*inv0, of[n][1]*inv0);
        *(float2*)(out + base1 + cc) = make_float2(of[n][2]*inv1, of[n][3]*inv1);
    }
}

// ============================================================================
// launch
// ============================================================================
extern "C" void kernel_launch(void* const* d_in, const int* in_sizes, int n_in,
                              void* d_out, int out_size)
{
    const float* x  = (const float*)d_in[0];
    const float* Wq = (const float*)d_in[1];
    const float* bq = (const float*)d_in[2];
    const float* Wk = (const float*)d_in[3];
    const float* bk = (const float*)d_in[4];
    const float* Wv = (const float*)d_in[5];
    const float* bv = (const float*)d_in[6];
    float* out = (float*)d_out;

    split_x<<<(long long)MM*EE/1024, 256>>>(x);
    split_w<<<(3*DD*EE)/256, 256>>>(Wq, Wk, Wv);

    cudaFuncSetAttribute(qkv_mma, cudaFuncAttributeMaxDynamicSharedMemorySize,
                         QKV_SMEM);
    qkv_mma<<<dim3(MM/64, 3), 256, QKV_SMEM>>>(bq, bk, bv);

    cudaFuncSetAttribute(flash_attn, cudaFuncAttributeMaxDynamicSharedMemorySize,
                         FLASH_SMEM);
    flash_attn<<<dim3(SS / QT, BB), 256, FLASH_SMEM>>>(out);
}